// round 4
// baseline (speedup 1.0000x reference)
#include <cuda_runtime.h>

// EfficientGCN preprocess, vectorized-store version.
// x: (N=128, C=3, T=300, V=25, M=2) fp32, conn: int32[25]
// out: (N, 3, 2C=6, T, V, M) fp32
//
// Innermost (V,M) = 50 floats/row; rows start at 200B offsets, so a float4 at
// float offset 50*t' + 2v is 16B aligned iff (t + v) is even.
//   t even: pairs (0,1)..(22,23) [slots 0..11], single v=24 [slot 12]
//   t odd : single v=0 [slot 0], pairs (1,2)..(23,24) [slots 1..12]
// One thread per (n, t, slot). Pair threads use float4 loads/stores
// (t and t+2 rows share parity -> aligned; t+1 row is misaligned -> 2x float2).

#define N_ 128
#define C_ 3
#define T_ 300
#define V_ 25
#define CST 15000      // 300*50 floats per (channel) slab
#define SLOTS 13

__global__ __launch_bounds__(256) void egcn_preprocess_v2(
    const float* __restrict__ x,
    const int* __restrict__ conn,
    float* __restrict__ out)
{
    int p = blockIdx.x * blockDim.x + threadIdx.x;
    // total = N_*T_*SLOTS = 499200, grid sized exactly

    int s  = p % SLOTS;
    int nt = p / SLOTS;
    int t  = nt % T_;
    int n  = nt / T_;

    const bool even_t  = (t & 1) == 0;
    const bool is_pair = even_t ? (s < 12) : (s > 0);
    int v0 = even_t ? (2 * s) : (2 * s - 1);
    if (v0 < 0) v0 = 0;                       // odd-t single slot

    const bool has_vel = (t < T_ - 2);

    const int ib    = (n * 3) * CST + t * 50;          // input, channel 0, row t
    const int obase = n * 18 * CST + t * 50 + 2 * v0;  // output, k=0

    if (is_pair) {
        const int pv0 = __ldg(&conn[v0]);
        const int pv1 = __ldg(&conn[v0 + 1]);

        float4 bv[3];

#pragma unroll
        for (int c = 0; c < C_; ++c) {
            const float* row = x + ib + c * CST;
            float4 a   = *(const float4*)(row + 2 * v0);     // aligned: t+v0 even
            float2 cen = *(const float2*)(row + 2);          // v=1 (broadcast)
            float2 pa  = *(const float2*)(row + 2 * pv0);
            float2 pb  = *(const float2*)(row + 2 * pv1);

            float4 d1, d2;
            if (has_vel) {
                float2 n1a = *(const float2*)(row + 50 + 2 * v0);      // t+1 misaligned
                float2 n1b = *(const float2*)(row + 50 + 2 * v0 + 2);
                float4 n2  = *(const float4*)(row + 100 + 2 * v0);     // t+2 aligned
                d1 = make_float4(n1a.x - a.x, n1a.y - a.y, n1b.x - a.z, n1b.y - a.w);
                d2 = make_float4(n2.x - a.x,  n2.y - a.y,  n2.z - a.z,  n2.w - a.w);
            } else {
                d1 = make_float4(0.f, 0.f, 0.f, 0.f);
                d2 = d1;
            }

            float* ob = out + obase + c * CST;
            *(float4*)(ob)             = a;                                    // joint: x
            *(float4*)(ob + 3 * CST)   = make_float4(a.x - cen.x, a.y - cen.y,
                                                     a.z - cen.x, a.w - cen.y); // x - center
            *(float4*)(ob + 6 * CST)   = d1;                                   // v1
            *(float4*)(ob + 9 * CST)   = d2;                                   // v2

            float4 b = make_float4(a.x - pa.x, a.y - pa.y, a.z - pb.x, a.w - pb.y);
            bv[c] = b;
            *(float4*)(ob + 12 * CST)  = b;                                    // bone vec
        }

        // per-(v,m) bone lengths over channels, then angles
        float lx = sqrtf(bv[0].x * bv[0].x + bv[1].x * bv[1].x + bv[2].x * bv[2].x) + 1e-4f;
        float ly = sqrtf(bv[0].y * bv[0].y + bv[1].y * bv[1].y + bv[2].y * bv[2].y) + 1e-4f;
        float lz = sqrtf(bv[0].z * bv[0].z + bv[1].z * bv[1].z + bv[2].z * bv[2].z) + 1e-4f;
        float lw = sqrtf(bv[0].w * bv[0].w + bv[1].w * bv[1].w + bv[2].w * bv[2].w) + 1e-4f;
        float rx = 1.0f / lx, ry = 1.0f / ly, rz = 1.0f / lz, rw = 1.0f / lw;

#pragma unroll
        for (int c = 0; c < C_; ++c) {
            float4 ang = make_float4(acosf(bv[c].x * rx), acosf(bv[c].y * ry),
                                     acosf(bv[c].z * rz), acosf(bv[c].w * rw));
            *(float4*)(out + obase + c * CST + 15 * CST) = ang;                // bone angle
        }
    } else {
        // single-joint path (v0 = 24 for even t, v0 = 0 for odd t)
        const int pv = __ldg(&conn[v0]);

        float2 bv[3];

#pragma unroll
        for (int c = 0; c < C_; ++c) {
            const float* row = x + ib + c * CST;
            float2 a   = *(const float2*)(row + 2 * v0);
            float2 cen = *(const float2*)(row + 2);
            float2 pa  = *(const float2*)(row + 2 * pv);

            float2 d1, d2;
            if (has_vel) {
                float2 n1 = *(const float2*)(row + 50 + 2 * v0);
                float2 n2 = *(const float2*)(row + 100 + 2 * v0);
                d1 = make_float2(n1.x - a.x, n1.y - a.y);
                d2 = make_float2(n2.x - a.x, n2.y - a.y);
            } else {
                d1 = make_float2(0.f, 0.f);
                d2 = d1;
            }

            float* ob = out + obase + c * CST;
            *(float2*)(ob)            = a;
            *(float2*)(ob + 3 * CST)  = make_float2(a.x - cen.x, a.y - cen.y);
            *(float2*)(ob + 6 * CST)  = d1;
            *(float2*)(ob + 9 * CST)  = d2;

            float2 b = make_float2(a.x - pa.x, a.y - pa.y);
            bv[c] = b;
            *(float2*)(ob + 12 * CST) = b;
        }

        float lx = sqrtf(bv[0].x * bv[0].x + bv[1].x * bv[1].x + bv[2].x * bv[2].x) + 1e-4f;
        float ly = sqrtf(bv[0].y * bv[0].y + bv[1].y * bv[1].y + bv[2].y * bv[2].y) + 1e-4f;
        float rx = 1.0f / lx, ry = 1.0f / ly;

#pragma unroll
        for (int c = 0; c < C_; ++c) {
            float2 ang = make_float2(acosf(bv[c].x * rx), acosf(bv[c].y * ry));
            *(float2*)(out + obase + c * CST + 15 * CST) = ang;
        }
    }
}

extern "C" void kernel_launch(void* const* d_in, const int* in_sizes, int n_in,
                              void* d_out, int out_size)
{
    const float* x  = (const float*)d_in[0];
    const int* conn = (const int*)d_in[1];
    float* out      = (float*)d_out;

    const int total = N_ * T_ * SLOTS;     // 499200
    const int threads = 256;
    const int blocks = total / threads;    // 1950 exactly
    egcn_preprocess_v2<<<blocks, threads>>>(x, conn, out);
}

// round 5
// speedup vs baseline: 1.3042x; 1.3042x over previous
#include <cuda_runtime.h>

// EfficientGCN preprocess on GB300 — v1 scheme (1 thread per (n,t,v), float2 over M),
// tuned for latency hiding: branchless clamped velocity loads (all LDGs front-batched)
// + occupancy raised via launch bounds (regs<=40 -> 6 blocks/SM).
//
// x: (N=128, C=3, T=300, V=25, M=2) fp32, conn: int32[25]
// out: (N, 3, 2C=6, T, V, M) fp32

#define N_ 128
#define C_ 3
#define T_ 300
#define V_ 25

__global__ __launch_bounds__(256, 6) void egcn_preprocess_v3(
    const float2* __restrict__ x2,
    const int* __restrict__ conn,
    float2* __restrict__ out2)
{
    const int P = N_ * T_ * V_;   // 960000
    int p = blockIdx.x * blockDim.x + threadIdx.x;
    if (p >= P) return;

    int v  = p % V_;
    int nt = p / V_;
    int t  = nt % T_;
    int n  = nt / T_;

    const int cstride = T_ * V_;                       // 7500 float2 per channel
    const int base    = n * (C_ * cstride) + t * V_;   // channel 0, row t

    const int pv = __ldg(&conn[v]);                    // parent joint

    // clamped row offsets for velocity loads — always legal, selected to 0 later
    const int d1off = (t < T_ - 1) ? V_ : 0;           // t+1 (clamped)
    const int d2off = (t < T_ - 2) ? 2 * V_ : 0;       // t+2 (clamped)
    const float sel = (t < T_ - 2) ? 1.0f : 0.0f;

    // ---- front-batched loads: 15 independent LDG.64 ----
    float2 a0, a1, a2, c0, c1, c2, p0, p1, p2, q0, q1, q2, r0, r1, r2;
    {
        const float2* row0 = x2 + base;
        const float2* row1 = row0 + cstride;
        const float2* row2 = row1 + cstride;
        a0 = row0[v];          a1 = row1[v];          a2 = row2[v];          // self
        q0 = row0[d1off + v];  q1 = row1[d1off + v];  q2 = row2[d1off + v];  // t+1
        r0 = row0[d2off + v];  r1 = row1[d2off + v];  r2 = row2[d2off + v];  // t+2
        c0 = row0[1];          c1 = row1[1];          c2 = row2[1];          // center
        p0 = row0[pv];         p1 = row1[pv];         p2 = row2[pv];         // parent
    }

    float2 a[3]   = {a0, a1, a2};
    float2 cen[3] = {c0, c1, c2};
    float2 par[3] = {p0, p1, p2};
    float2 n1[3]  = {q0, q1, q2};
    float2 n2[3]  = {r0, r1, r2};

    float2 d1[3], d2[3], bv[3];
#pragma unroll
    for (int c = 0; c < C_; ++c) {
        d1[c] = make_float2((n1[c].x - a[c].x) * sel, (n1[c].y - a[c].y) * sel);
        d2[c] = make_float2((n2[c].x - a[c].x) * sel, (n2[c].y - a[c].y) * sel);
        bv[c] = make_float2(a[c].x - par[c].x, a[c].y - par[c].y);
    }

    float lx = sqrtf(bv[0].x * bv[0].x + bv[1].x * bv[1].x + bv[2].x * bv[2].x) + 1e-4f;
    float ly = sqrtf(bv[0].y * bv[0].y + bv[1].y * bv[1].y + bv[2].y * bv[2].y) + 1e-4f;
    float rlx = 1.0f / lx;
    float rly = 1.0f / ly;

    float2 ang[3];
#pragma unroll
    for (int c = 0; c < C_; ++c) {
        ang[c].x = acosf(bv[c].x * rlx);
        ang[c].y = acosf(bv[c].y * rly);
    }

    // ---- stores: 18 STG.64, each slab contiguous across the warp ----
    const int ostride = T_ * V_;                        // 7500 float2 per (b,c2)
    const int obase   = n * 18 * ostride + t * V_ + v;  // b=0,c2=0

#pragma unroll
    for (int c = 0; c < C_; ++c) {
        out2[obase + (c     ) * ostride] = a[c];                               // joint: x
        out2[obase + (c + 3 ) * ostride] =
            make_float2(a[c].x - cen[c].x, a[c].y - cen[c].y);                 // x - center
        out2[obase + (c + 6 ) * ostride] = d1[c];                              // v1
        out2[obase + (c + 9 ) * ostride] = d2[c];                              // v2
        out2[obase + (c + 12) * ostride] = bv[c];                              // bone vec
        out2[obase + (c + 15) * ostride] = ang[c];                             // bone angle
    }
}

extern "C" void kernel_launch(void* const* d_in, const int* in_sizes, int n_in,
                              void* d_out, int out_size)
{
    const float2* x2  = (const float2*)d_in[0];
    const int* conn   = (const int*)d_in[1];
    float2* out2      = (float2*)d_out;

    const int P = N_ * T_ * V_;          // 960000
    const int threads = 256;
    const int blocks = (P + threads - 1) / threads;   // 3750
    egcn_preprocess_v3<<<blocks, threads>>>(x2, conn, out2);
}

// round 7
// speedup vs baseline: 1.5317x; 1.1744x over previous
#include <cuda_runtime.h>

// EfficientGCN preprocess on GB300 — shared-memory tiled version.
// x: (N=128, C=3, T=300, V=25, M=2) fp32, conn: int32[25]
// out: (N, 3, 6, T, V, M) fp32
//
// One block = one (n, 10-row t-tile). Stage 3ch x 12rows x 50 floats (7.2KB)
// into smem with coalesced float4 loads, then each thread computes one (t,v)
// point reading self/center/parent/t+1/t+2 from smem. Stores are streaming
// (__stcs) since the output is write-once.

#define N_ 128
#define C_ 3
#define T_ 300
#define V_ 25
#define RPT 10            // t-rows computed per tile
#define TILE_ROWS 12      // RPT + 2 halo
#define TILES_PER_N 30    // 300 / 10
#define ROWF 50           // floats per (t) row  (V*M)
#define CSLAB 15000       // floats per channel slab (T*ROWF)
#define SM_CH 600         // floats per channel in smem (TILE_ROWS*ROWF)

__global__ __launch_bounds__(256, 6) void egcn_preprocess_v4(
    const float* __restrict__ x,
    const int* __restrict__ conn,
    float* __restrict__ out)
{
    __shared__ float sm[C_ * SM_CH];          // 1800 floats = 7.2 KB

    const int tid  = threadIdx.x;
    const int n    = blockIdx.x / TILES_PER_N;
    const int tile = blockIdx.x % TILES_PER_N;
    const int t0   = tile * RPT;

    const float* xn = x + n * (C_ * CSLAB);

    // ---- stage tile into smem ----
    if (t0 + TILE_ROWS <= T_) {
        // fast path: 3 channels x 600 contiguous floats = 450 float4, aligned
        #pragma unroll
        for (int k = 0; k < 2; ++k) {
            int idx = tid + k * 256;
            if (idx < 450) {
                int c   = idx / 150;
                int rem = idx - c * 150;
                const float4* src = (const float4*)(xn + c * CSLAB + t0 * ROWF);
                ((float4*)(sm + c * SM_CH))[rem] = src[rem];
            }
        }
    } else {
        // last tile (t0 = 290): per-float2 row clamp
        for (int idx = tid; idx < C_ * TILE_ROWS * V_; idx += 256) {
            int c   = idx / (TILE_ROWS * V_);
            int rem = idx - c * (TILE_ROWS * V_);
            int r   = rem / V_;
            int v   = rem - r * V_;
            int gt  = t0 + r; if (gt > T_ - 1) gt = T_ - 1;
            ((float2*)(sm + c * SM_CH + r * ROWF))[v] =
                ((const float2*)(xn + c * CSLAB + gt * ROWF))[v];
        }
    }
    __syncthreads();

    if (tid >= RPT * V_) return;              // 250 active compute threads

    const int r = tid / V_;                   // 0..9
    const int v = tid - r * V_;               // 0..24
    const int t = t0 + r;
    const int pv = conn[v];

    const float sel = (t < T_ - 2) ? 1.0f : 0.0f;

    float2 a[3], cen[3], par[3], d1[3], d2[3], bv[3];
#pragma unroll
    for (int c = 0; c < C_; ++c) {
        const float* base = sm + c * SM_CH + r * ROWF;
        a[c]   = ((const float2*)base)[v];
        cen[c] = ((const float2*)base)[1];
        par[c] = ((const float2*)base)[pv];
        float2 n1 = ((const float2*)(base + ROWF))[v];       // t+1 (halo)
        float2 n2 = ((const float2*)(base + 2 * ROWF))[v];   // t+2 (halo)
        d1[c] = make_float2((n1.x - a[c].x) * sel, (n1.y - a[c].y) * sel);
        d2[c] = make_float2((n2.x - a[c].x) * sel, (n2.y - a[c].y) * sel);
        bv[c] = make_float2(a[c].x - par[c].x, a[c].y - par[c].y);
    }

    float lx = sqrtf(bv[0].x * bv[0].x + bv[1].x * bv[1].x + bv[2].x * bv[2].x) + 1e-4f;
    float ly = sqrtf(bv[0].y * bv[0].y + bv[1].y * bv[1].y + bv[2].y * bv[2].y) + 1e-4f;
    float rlx = 1.0f / lx;
    float rly = 1.0f / ly;

    float2 ang[3];
#pragma unroll
    for (int c = 0; c < C_; ++c) {
        ang[c].x = acosf(bv[c].x * rlx);
        ang[c].y = acosf(bv[c].y * rly);
    }

    // ---- 18 streaming STG.64, each slab contiguous across the block ----
    const int ostride = T_ * V_;                          // 7500 float2 per (b,c2)
    float2* ob = (float2*)out + (size_t)n * 18 * ostride + t * V_ + v;

#pragma unroll
    for (int c = 0; c < C_; ++c) {
        __stcs(ob + (c     ) * ostride, a[c]);                                  // joint: x
        __stcs(ob + (c + 3 ) * ostride,
               make_float2(a[c].x - cen[c].x, a[c].y - cen[c].y));              // x - center
        __stcs(ob + (c + 6 ) * ostride, d1[c]);                                 // v1
        __stcs(ob + (c + 9 ) * ostride, d2[c]);                                 // v2
        __stcs(ob + (c + 12) * ostride, bv[c]);                                 // bone vec
        __stcs(ob + (c + 15) * ostride, ang[c]);                                // bone angle
    }
}

extern "C" void kernel_launch(void* const* d_in, const int* in_sizes, int n_in,
                              void* d_out, int out_size)
{
    const float* x  = (const float*)d_in[0];
    const int* conn = (const int*)d_in[1];
    float* out      = (float*)d_out;

    const int blocks = N_ * TILES_PER_N;     // 3840
    egcn_preprocess_v4<<<blocks, 256>>>(x, conn, out);
}